// round 15
// baseline (speedup 1.0000x reference)
#include <cuda_runtime.h>
#include <math.h>

#define T_LEN 32768
#define I_DIM 128
#define H_DIM 512
#define G_DIM 2048
#define NHEAD 25
#define NCTA 64
#define RING 8
#define WDOG (1u << 28)   // poll watchdog: unreachable unless pipeline is wedged

// Device-global scratch (no allocation allowed anywhere).
__device__ float g_xg[T_LEN * G_DIM];     // permuted pre-activations (268 MB)
__device__ float g_part[T_LEN * NCTA];    // per-step per-CTA head partials (8 MB)
__device__ float g_v[H_DIM];              // fused head vector v = W1^T Wout^T
__device__ float g_c0;                    // fused head constant b1 . Wout
// Per-consumer replicated mailboxes: (h bits low 32, step tag high 32).
// Consumer CTA c polls ONLY g_mbox[slot][c][*] -> zero cross-CTA line sharing.
__device__ __align__(128) unsigned long long g_mbox[RING][NCTA][H_DIM];   // 2 MB

// f32x2 packed FMA (sm_100+): d = a*b + c on two packed floats.
__device__ __forceinline__ unsigned long long fma2(unsigned long long a,
                                                   unsigned long long b,
                                                   unsigned long long c) {
    unsigned long long d;
    asm("fma.rn.f32x2 %0, %1, %2, %3;" : "=l"(d) : "l"(a), "l"(b), "l"(c));
    return d;
}

__device__ __forceinline__ float fsigmoid(float x) {
    return __fdividef(1.f, 1.f + __expf(-x));
}
__device__ __forceinline__ float ftanh_fast(float x) {
    // 1 - 2/(e^{2x}+1); saturates cleanly at +-1 for large |x|.
    return 1.f - 2.f * __fdividef(1.f, __expf(2.f * x) + 1.f);
}

// ---------------------------------------------------------------------------
// Kernel 0a: init all mailboxes (graph-replay safe). Slot 0 = (h=0, tag=0)
// for every consumer; all other slots tag-poisoned.
// ---------------------------------------------------------------------------
__global__ __launch_bounds__(256) void mbox_init_kernel() {
    const int total = RING * NCTA * H_DIM;
    unsigned long long* flat = &g_mbox[0][0][0];
    int stride = gridDim.x * blockDim.x;
    for (int i = blockIdx.x * blockDim.x + threadIdx.x; i < total; i += stride)
        flat[i] = (i < NCTA * H_DIM) ? 0ull : 0xFFFFFFFF00000000ull;
}

// ---------------------------------------------------------------------------
// Kernel 0b: fuse head weights.
// ---------------------------------------------------------------------------
__global__ void prep_kernel(const float* __restrict__ W1,
                            const float* __restrict__ b1,
                            const float* __restrict__ Wout) {
    int tid = threadIdx.x;
    if (tid < H_DIM) {
        float s = 0.f;
        for (int k = 0; k < NHEAD; k++) s += Wout[k] * W1[k * H_DIM + tid];
        g_v[tid] = s;
    }
    if (tid == 0) {
        float s = 0.f;
        for (int k = 0; k < NHEAD; k++) s += b1[k] * Wout[k];
        g_c0 = s;
    }
}

// ---------------------------------------------------------------------------
// Kernel 1: xg[t, colp] = x[t] . W_ih[grow] + (b_ih+b_hh)[grow], permuted so
// warp u of the LSTM kernel reads one float4 (i,f,g,o for its unit):
//   colp = u*4 + gate,  grow = gate*512 + u.
// ---------------------------------------------------------------------------
__global__ __launch_bounds__(256) void xg_kernel(const float* __restrict__ x,
                                                 const float* __restrict__ W_ih,
                                                 const float* __restrict__ b_ih,
                                                 const float* __restrict__ b_hh) {
    __shared__ float Xs[32][I_DIM];
    int tb    = blockIdx.x;       // 0..1023 (32 timesteps each)
    int cb    = blockIdx.y;       // 0..7    (256 columns each)
    int tid   = threadIdx.x;
    int tbase = tb * 32;

    for (int idx = tid; idx < 32 * I_DIM; idx += 256)
        Xs[idx >> 7][idx & 127] = x[(tbase + (idx >> 7)) * I_DIM + (idx & 127)];
    __syncthreads();

    int col  = cb * 256 + tid;            // permuted column
    int u    = col >> 2;
    int gate = col & 3;
    int grow = gate * 512 + u;
    float bias = b_ih[grow] + b_hh[grow];

    float acc[32];
#pragma unroll
    for (int tt = 0; tt < 32; tt++) acc[tt] = bias;

    const float4* Wr = (const float4*)(W_ih + grow * I_DIM);
    for (int kq = 0; kq < 32; kq++) {
        float4 w4 = Wr[kq];
#pragma unroll
        for (int tt = 0; tt < 32; tt++) {
            float4 x4 = *(const float4*)&Xs[tt][kq * 4];
            acc[tt] += w4.x * x4.x + w4.y * x4.y + w4.z * x4.z + w4.w * x4.w;
        }
    }
#pragma unroll
    for (int tt = 0; tt < 32; tt++)
        g_xg[(tbase + tt) * G_DIM + col] = acc[tt];
}

// ---------------------------------------------------------------------------
// Kernel 2: persistent sequential LSTM. 64 CTAs x 256 threads.
// Warp w of CTA cb owns unit u = cb*8+w, W_hh slice register-resident.
// Per step: each thread polls the 2 pairs it owns in its CTA's PRIVATE
// mailbox replica (no cross-CTA line sharing -> no LTS hot-line queueing),
// stages h into a double-buffered smem array; ONE barrier; packed-f32x2
// matvec + shfl butterfly (result in ALL lanes); every lane redundantly runs
// the cell (deterministic) and publishes (h, tag=t+1) to its 2 assigned
// consumer replicas with scalar atomic 8B st.relaxed.gpu.
// Ring safety (as in the passing R5): overwriting slot (t+1)%8 (old tag t-7)
// requires passing the step-t poll => all CTAs finished step t-1 => all
// consumed their slot-(t+1)%8 pairs back at step t-7.
// ---------------------------------------------------------------------------
__global__ __launch_bounds__(256, 1) void lstm_kernel(const float* __restrict__ W_hh) {
    __shared__ float hbuf[2][H_DIM];
    __shared__ float pbuf[2][8];
    __shared__ int   dead;
    int tid = threadIdx.x;
    int w   = tid >> 5;
    int l   = tid & 31;
    int cb  = blockIdx.x;
    int u   = cb * 8 + w;

    if (tid == 0) dead = 0;

    // Register-resident W_hh: row r (gate) covers h[4l+128m .. +4).
    float4 wr[4][4];
#pragma unroll
    for (int r = 0; r < 4; r++) {
        const float* row = W_hh + (r * 512 + u) * H_DIM;
#pragma unroll
        for (int m = 0; m < 4; m++)
            wr[r][m] = *(const float4*)(row + 4 * l + 128 * m);
    }

    float cstate = 0.f;                       // redundant per-lane (identical)
    float vval   = (l == 0) ? g_v[u] : 0.f;

    // All lanes load the warp-uniform xg float4 (single broadcast transaction).
    float4 xg4 = *(const float4*)&g_xg[0 * G_DIM + u * 4];
    __syncthreads();

    for (int t = 0; t < T_LEN; t++) {
        int buf = t & 1;

        // Prefetch next step's gate pre-activations (DRAM latency hidden).
        float4 xg_next = make_float4(0.f, 0.f, 0.f, 0.f);
        if (t + 1 < T_LEN)
            xg_next = *(const float4*)&g_xg[(t + 1) * G_DIM + u * 4];

        // Poll the 2 pairs this thread owns in OUR private replica.
        {
            const unsigned long long* p0 = &g_mbox[t & (RING - 1)][cb][2 * tid];
            unsigned long long v0, v1;
            unsigned long long want = ((unsigned long long)(unsigned)t) << 32;
            unsigned int spins = 0;
            do {
                asm volatile("ld.relaxed.gpu.global.b64 %0, [%1];"
                             : "=l"(v0) : "l"(p0) : "memory");
                asm volatile("ld.relaxed.gpu.global.b64 %0, [%1];"
                             : "=l"(v1) : "l"(p0 + 1) : "memory");
                if (++spins >= WDOG) { dead = 1; break; }     // watchdog
            } while ((v0 & 0xFFFFFFFF00000000ull) != want ||
                     (v1 & 0xFFFFFFFF00000000ull) != want);
            hbuf[buf][2 * tid]     = __uint_as_float((unsigned)v0);
            hbuf[buf][2 * tid + 1] = __uint_as_float((unsigned)(v1));
        }
        __syncthreads();          // the ONLY barrier per step
        if (dead) break;

        // Matvec: 4 gate rows x 16 h-elems per lane, packed f32x2.
        unsigned long long acc2[4] = {0ull, 0ull, 0ull, 0ull};
#pragma unroll
        for (int m = 0; m < 4; m++) {
            float4 h4 = *(const float4*)&hbuf[buf][4 * l + 128 * m];
            unsigned long long hlo = *(const unsigned long long*)&h4.x;
            unsigned long long hhi = *(const unsigned long long*)&h4.z;
#pragma unroll
            for (int r = 0; r < 4; r++) {
                unsigned long long wlo = *(const unsigned long long*)&wr[r][m].x;
                unsigned long long whi = *(const unsigned long long*)&wr[r][m].z;
                acc2[r] = fma2(wlo, hlo, acc2[r]);
                acc2[r] = fma2(whi, hhi, acc2[r]);
            }
        }
        float acc[4];
#pragma unroll
        for (int r = 0; r < 4; r++) {
            unsigned int lo = (unsigned int)acc2[r];
            unsigned int hi = (unsigned int)(acc2[r] >> 32);
            acc[r] = __uint_as_float(lo) + __uint_as_float(hi);
        }
#pragma unroll
        for (int off = 16; off > 0; off >>= 1) {
#pragma unroll
            for (int r = 0; r < 4; r++)
                acc[r] += __shfl_xor_sync(0xffffffffu, acc[r], off);
        }
        // Butterfly leaves the full sums in EVERY lane.

        // All lanes: redundant deterministic cell; each lane publishes to its
        // 2 assigned consumer replicas.
        {
            float iv = fsigmoid(acc[0] + xg4.x);
            float fv = fsigmoid(acc[1] + xg4.y);
            float gv = ftanh_fast(acc[2] + xg4.z);
            float ov = fsigmoid(acc[3] + xg4.w);
            cstate = fv * cstate + iv * gv;
            float hv = ov * ftanh_fast(cstate);
            unsigned long long pairv =
                ((unsigned long long)(unsigned)(t + 1) << 32) |
                (unsigned long long)__float_as_uint(hv);
            int nslot = (t + 1) & (RING - 1);
            int c0 = 2 * l;
            asm volatile("st.relaxed.gpu.global.b64 [%0], %1;"
                         :: "l"(&g_mbox[nslot][c0][u]), "l"(pairv) : "memory");
            asm volatile("st.relaxed.gpu.global.b64 [%0], %1;"
                         :: "l"(&g_mbox[nslot][c0 + 1][u]), "l"(pairv) : "memory");
            if (l == 0) pbuf[buf][w] = hv * vval;
        }

        // Off critical path: previous step's per-CTA head partial (pbuf[buf^1]
        // was completed before this step's barrier).
        if (tid == 0 && t > 0) {
            float* pb = pbuf[buf ^ 1];
            float s = pb[0] + pb[1] + pb[2] + pb[3] + pb[4] + pb[5] + pb[6] + pb[7];
            g_part[(t - 1) * NCTA + cb] = s;
        }
        xg4 = xg_next;
    }

    __syncthreads();
    if (tid == 0) {   // final step's head partial
        float* pb = pbuf[(T_LEN - 1) & 1];
        float s = pb[0] + pb[1] + pb[2] + pb[3] + pb[4] + pb[5] + pb[6] + pb[7];
        g_part[(T_LEN - 1) * NCTA + cb] = s;
    }
}

// ---------------------------------------------------------------------------
// Kernel 3: out[t] = c0 + sum_cb g_part[t][cb]
// ---------------------------------------------------------------------------
__global__ void head_kernel(float* __restrict__ out) {
    int t = blockIdx.x * blockDim.x + threadIdx.x;
    if (t >= T_LEN) return;
    float s = g_c0;
    const float4* p = (const float4*)&g_part[t * NCTA];
#pragma unroll
    for (int q = 0; q < NCTA / 4; q++) {
        float4 v = p[q];
        s += v.x + v.y + v.z + v.w;
    }
    out[t] = s;
}

// ---------------------------------------------------------------------------
extern "C" void kernel_launch(void* const* d_in, const int* in_sizes, int n_in,
                              void* d_out, int out_size) {
    const float* x    = (const float*)d_in[0];
    const float* W_ih = (const float*)d_in[1];
    const float* W_hh = (const float*)d_in[2];
    const float* b_ih = (const float*)d_in[3];
    const float* b_hh = (const float*)d_in[4];
    const float* W1   = (const float*)d_in[5];
    const float* b1   = (const float*)d_in[6];
    const float* Wout = (const float*)d_in[7];
    float* out = (float*)d_out;

    (void)in_sizes; (void)n_in; (void)out_size;

    mbox_init_kernel<<<256, 256>>>();
    prep_kernel<<<1, 512>>>(W1, b1, Wout);
    dim3 gx(T_LEN / 32, G_DIM / 256);
    xg_kernel<<<gx, 256>>>(x, W_ih, b_ih, b_hh);
    lstm_kernel<<<NCTA, 256>>>(W_hh);
    head_kernel<<<T_LEN / 256, 256>>>(out);
}

// round 16
// speedup vs baseline: 1.2021x; 1.2021x over previous
#include <cuda_runtime.h>
#include <math.h>

#define T_LEN 32768
#define I_DIM 128
#define H_DIM 512
#define G_DIM 2048
#define NHEAD 25
#define NCTA 64
#define RING 8
#define WDOG (1u << 28)   // poll watchdog: unreachable unless pipeline is wedged

// Device-global scratch (no allocation allowed anywhere).
__device__ float g_xg[T_LEN * G_DIM];     // permuted pre-activations (268 MB)
__device__ float g_part[T_LEN * NCTA];    // per-step per-CTA head partials (8 MB)
__device__ float g_v[H_DIM];              // fused head vector v = W1^T Wout^T
__device__ float g_c0;                    // fused head constant b1 . Wout
// Shared ring of (h bits low 32, step tag high 32) pairs — the R5 layout.
__device__ __align__(128) unsigned long long g_hpair[RING][H_DIM];   // 32 KB

// f32x2 packed FMA (sm_100+): d = a*b + c on two packed floats.
__device__ __forceinline__ unsigned long long fma2(unsigned long long a,
                                                   unsigned long long b,
                                                   unsigned long long c) {
    unsigned long long d;
    asm("fma.rn.f32x2 %0, %1, %2, %3;" : "=l"(d) : "l"(a), "l"(b), "l"(c));
    return d;
}

__device__ __forceinline__ float fsigmoid(float x) {
    return __fdividef(1.f, 1.f + __expf(-x));
}
__device__ __forceinline__ float ftanh_fast(float x) {
    // 1 - 2/(e^{2x}+1); saturates cleanly at +-1 for large |x|.
    return 1.f - 2.f * __fdividef(1.f, __expf(2.f * x) + 1.f);
}

// ---------------------------------------------------------------------------
// Kernel 0: fuse head weights; re-init ALL ring words (graph-replay safe).
// ---------------------------------------------------------------------------
__global__ void prep_kernel(const float* __restrict__ W1,
                            const float* __restrict__ b1,
                            const float* __restrict__ Wout) {
    int tid = threadIdx.x;
    if (tid < H_DIM) {
        float s = 0.f;
        for (int k = 0; k < NHEAD; k++) s += Wout[k] * W1[k * H_DIM + tid];
        g_v[tid] = s;
        // slot 0 carries h(0)=0 with tag 0 (consumed at t=0); others poisoned.
        g_hpair[0][tid] = 0ull;
        for (int m = 1; m < RING; m++)
            g_hpair[m][tid] = 0xFFFFFFFF00000000ull;
    }
    if (tid == 0) {
        float s = 0.f;
        for (int k = 0; k < NHEAD; k++) s += b1[k] * Wout[k];
        g_c0 = s;
    }
}

// ---------------------------------------------------------------------------
// Kernel 1: xg[t, colp] = x[t] . W_ih[grow] + (b_ih+b_hh)[grow], permuted so
// warp u of the LSTM kernel reads one float4 (i,f,g,o for its unit):
//   colp = u*4 + gate,  grow = gate*512 + u.
// ---------------------------------------------------------------------------
__global__ __launch_bounds__(256) void xg_kernel(const float* __restrict__ x,
                                                 const float* __restrict__ W_ih,
                                                 const float* __restrict__ b_ih,
                                                 const float* __restrict__ b_hh) {
    __shared__ float Xs[32][I_DIM];
    int tb    = blockIdx.x;       // 0..1023 (32 timesteps each)
    int cb    = blockIdx.y;       // 0..7    (256 columns each)
    int tid   = threadIdx.x;
    int tbase = tb * 32;

    for (int idx = tid; idx < 32 * I_DIM; idx += 256)
        Xs[idx >> 7][idx & 127] = x[(tbase + (idx >> 7)) * I_DIM + (idx & 127)];
    __syncthreads();

    int col  = cb * 256 + tid;            // permuted column
    int u    = col >> 2;
    int gate = col & 3;
    int grow = gate * 512 + u;
    float bias = b_ih[grow] + b_hh[grow];

    float acc[32];
#pragma unroll
    for (int tt = 0; tt < 32; tt++) acc[tt] = bias;

    const float4* Wr = (const float4*)(W_ih + grow * I_DIM);
    for (int kq = 0; kq < 32; kq++) {
        float4 w4 = Wr[kq];
#pragma unroll
        for (int tt = 0; tt < 32; tt++) {
            float4 x4 = *(const float4*)&Xs[tt][kq * 4];
            acc[tt] += w4.x * x4.x + w4.y * x4.y + w4.z * x4.z + w4.w * x4.w;
        }
    }
#pragma unroll
    for (int tt = 0; tt < 32; tt++)
        g_xg[(tbase + tt) * G_DIM + col] = acc[tt];
}

// ---------------------------------------------------------------------------
// Kernel 2: persistent sequential LSTM — R5 architecture (best) + 3 deltas:
//   (1) poll both adjacent pairs with ONE ld.relaxed.gpu.v2.b64 (halves L2
//       request demand: was exactly at slice saturation with two 8B loads),
//   (2) single barrier/step via double-buffered hbuf/pbuf,
//   (3) bounded-poll watchdog (no un-killable hangs).
// 64 CTAs x 256 threads; warp w of CTA cb owns unit u = cb*8+w (gate rows
// u, 512+u, 1024+u, 1536+u); W_hh slice register-resident. Lane 0 runs the
// cell and publishes (h, tag=t+1) with ONE scalar 8B st.relaxed.gpu.
// Ring safety: publishing tag t+1 requires passing the step-t poll => all
// CTAs finished step t-1 => all consumed the overwritten tag (t-7) long ago.
// ---------------------------------------------------------------------------
__global__ __launch_bounds__(256, 1) void lstm_kernel(const float* __restrict__ W_hh) {
    __shared__ float hbuf[2][H_DIM];
    __shared__ float pbuf[2][8];
    __shared__ int   dead;
    int tid = threadIdx.x;
    int w   = tid >> 5;
    int l   = tid & 31;
    int cb  = blockIdx.x;
    int u   = cb * 8 + w;

    if (tid == 0) dead = 0;

    // Register-resident W_hh: row r (gate) covers h[4l+128m .. +4).
    float4 wr[4][4];
#pragma unroll
    for (int r = 0; r < 4; r++) {
        const float* row = W_hh + (r * 512 + u) * H_DIM;
#pragma unroll
        for (int m = 0; m < 4; m++)
            wr[r][m] = *(const float4*)(row + 4 * l + 128 * m);
    }

    float cstate = 0.f;
    float vval   = (l == 0) ? g_v[u] : 0.f;

    // Warp-uniform xg float4 (broadcast; one transaction).
    float4 xg4 = *(const float4*)&g_xg[0 * G_DIM + u * 4];
    __syncthreads();

    for (int t = 0; t < T_LEN; t++) {
        int buf = t & 1;

        // Prefetch next step's gate pre-activations (DRAM latency hidden).
        float4 xg_next = make_float4(0.f, 0.f, 0.f, 0.f);
        if (t + 1 < T_LEN)
            xg_next = *(const float4*)&g_xg[(t + 1) * G_DIM + u * 4];

        // Poll BOTH adjacent pairs with one 16B vector load (each 8B element
        // individually single-copy atomic).
        {
            const unsigned long long* p0 = &g_hpair[t & (RING - 1)][2 * tid];
            unsigned long long v0, v1;
            unsigned long long want = ((unsigned long long)(unsigned)t) << 32;
            unsigned int spins = 0;
            do {
                asm volatile("ld.relaxed.gpu.global.v2.b64 {%0,%1}, [%2];"
                             : "=l"(v0), "=l"(v1) : "l"(p0) : "memory");
                if (++spins >= WDOG) { dead = 1; break; }     // watchdog
            } while ((v0 & 0xFFFFFFFF00000000ull) != want ||
                     (v1 & 0xFFFFFFFF00000000ull) != want);
            hbuf[buf][2 * tid]     = __uint_as_float((unsigned)v0);
            hbuf[buf][2 * tid + 1] = __uint_as_float((unsigned)v1);
        }
        __syncthreads();          // the ONLY barrier per step
        if (dead) break;

        // Matvec: 4 gate rows x 16 h-elems per lane, packed f32x2.
        unsigned long long acc2[4] = {0ull, 0ull, 0ull, 0ull};
#pragma unroll
        for (int m = 0; m < 4; m++) {
            float4 h4 = *(const float4*)&hbuf[buf][4 * l + 128 * m];   // conflict-free
            unsigned long long hlo = *(const unsigned long long*)&h4.x;
            unsigned long long hhi = *(const unsigned long long*)&h4.z;
#pragma unroll
            for (int r = 0; r < 4; r++) {
                unsigned long long wlo = *(const unsigned long long*)&wr[r][m].x;
                unsigned long long whi = *(const unsigned long long*)&wr[r][m].z;
                acc2[r] = fma2(wlo, hlo, acc2[r]);
                acc2[r] = fma2(whi, hhi, acc2[r]);
            }
        }
        float acc[4];
#pragma unroll
        for (int r = 0; r < 4; r++) {
            unsigned int lo = (unsigned int)acc2[r];
            unsigned int hi = (unsigned int)(acc2[r] >> 32);
            acc[r] = __uint_as_float(lo) + __uint_as_float(hi);
        }
#pragma unroll
        for (int off = 16; off > 0; off >>= 1) {
#pragma unroll
            for (int r = 0; r < 4; r++)
                acc[r] += __shfl_xor_sync(0xffffffffu, acc[r], off);
        }

        // Lane 0: LSTM cell + single fused atomic 8B publish of (h, tag=t+1).
        if (l == 0) {
            float iv = fsigmoid(acc[0] + xg4.x);
            float fv = fsigmoid(acc[1] + xg4.y);
            float gv = ftanh_fast(acc[2] + xg4.z);
            float ov = fsigmoid(acc[3] + xg4.w);
            cstate = fv * cstate + iv * gv;
            float hv = ov * ftanh_fast(cstate);
            unsigned long long pairv =
                ((unsigned long long)(unsigned)(t + 1) << 32) |
                (unsigned long long)__float_as_uint(hv);
            asm volatile("st.relaxed.gpu.global.b64 [%0], %1;"
                         :: "l"(&g_hpair[(t + 1) & (RING - 1)][u]), "l"(pairv)
                         : "memory");
            pbuf[buf][w] = hv * vval;
        }

        // Off critical path: previous step's head partial (pbuf[buf^1] was
        // completed by all warps before they arrived at this step's barrier).
        if (tid == 0 && t > 0) {
            float* pb = pbuf[buf ^ 1];
            float s = pb[0] + pb[1] + pb[2] + pb[3]
                    + pb[4] + pb[5] + pb[6] + pb[7];
            g_part[(t - 1) * NCTA + cb] = s;
        }
        xg4 = xg_next;
    }

    __syncthreads();
    if (tid == 0) {   // final step's head partial
        float* pb = pbuf[(T_LEN - 1) & 1];
        float s = pb[0] + pb[1] + pb[2] + pb[3] + pb[4] + pb[5] + pb[6] + pb[7];
        g_part[(T_LEN - 1) * NCTA + cb] = s;
    }
}

// ---------------------------------------------------------------------------
// Kernel 3: out[t] = c0 + sum_cb g_part[t][cb]
// ---------------------------------------------------------------------------
__global__ void head_kernel(float* __restrict__ out) {
    int t = blockIdx.x * blockDim.x + threadIdx.x;
    if (t >= T_LEN) return;
    float s = g_c0;
    const float4* p = (const float4*)&g_part[t * NCTA];
#pragma unroll
    for (int q = 0; q < NCTA / 4; q++) {
        float4 v = p[q];
        s += v.x + v.y + v.z + v.w;
    }
    out[t] = s;
}

// ---------------------------------------------------------------------------
extern "C" void kernel_launch(void* const* d_in, const int* in_sizes, int n_in,
                              void* d_out, int out_size) {
    const float* x    = (const float*)d_in[0];
    const float* W_ih = (const float*)d_in[1];
    const float* W_hh = (const float*)d_in[2];
    const float* b_ih = (const float*)d_in[3];
    const float* b_hh = (const float*)d_in[4];
    const float* W1   = (const float*)d_in[5];
    const float* b1   = (const float*)d_in[6];
    const float* Wout = (const float*)d_in[7];
    float* out = (float*)d_out;

    (void)in_sizes; (void)n_in; (void)out_size;

    prep_kernel<<<1, 512>>>(W1, b1, Wout);
    dim3 gx(T_LEN / 32, G_DIM / 256);
    xg_kernel<<<gx, 256>>>(x, W_ih, b_ih, b_hh);
    lstm_kernel<<<NCTA, 256>>>(W_hh);
    head_kernel<<<T_LEN / 256, 256>>>(out);
}

// round 17
// speedup vs baseline: 1.5591x; 1.2970x over previous
#include <cuda_runtime.h>
#include <math.h>

#define T_LEN 32768
#define I_DIM 128
#define H_DIM 512
#define G_DIM 2048
#define NHEAD 25
#define NCTA 64
#define RING 8
#define NREP 4
#define WDOG (1u << 28)   // poll watchdog: unreachable unless pipeline is wedged

// Device-global scratch (no allocation allowed anywhere).
__device__ float g_xg[T_LEN * G_DIM];     // permuted pre-activations (268 MB)
__device__ float g_part[T_LEN * NCTA];    // per-step per-CTA head partials (8 MB)
__device__ float g_v[H_DIM];              // fused head vector v = W1^T Wout^T
__device__ float g_c0;                    // fused head constant b1 . Wout
// Ring of (h bits low 32, step tag high 32) pairs, replicated x4: consumer CTA
// cb polls ONLY replica cb&3 -> 16 CTAs/line -> 0.26 sect/cy/line (was 1.02 =
// LTS slice saturation with all 64 CTAs on one copy).
__device__ __align__(128) unsigned long long g_hpair[RING][NREP][H_DIM];  // 128 KB

// f32x2 packed FMA (sm_100+): d = a*b + c on two packed floats.
__device__ __forceinline__ unsigned long long fma2(unsigned long long a,
                                                   unsigned long long b,
                                                   unsigned long long c) {
    unsigned long long d;
    asm("fma.rn.f32x2 %0, %1, %2, %3;" : "=l"(d) : "l"(a), "l"(b), "l"(c));
    return d;
}

__device__ __forceinline__ float fsigmoid(float x) {
    return __fdividef(1.f, 1.f + __expf(-x));
}
__device__ __forceinline__ float ftanh_fast(float x) {
    // 1 - 2/(e^{2x}+1); saturates cleanly at +-1 for large |x|.
    return 1.f - 2.f * __fdividef(1.f, __expf(2.f * x) + 1.f);
}

// ---------------------------------------------------------------------------
// Kernel 0: fuse head weights; re-init ALL ring words in ALL replicas
// (graph-replay safe).
// ---------------------------------------------------------------------------
__global__ void prep_kernel(const float* __restrict__ W1,
                            const float* __restrict__ b1,
                            const float* __restrict__ Wout) {
    int tid = threadIdx.x;
    if (tid < H_DIM) {
        float s = 0.f;
        for (int k = 0; k < NHEAD; k++) s += Wout[k] * W1[k * H_DIM + tid];
        g_v[tid] = s;
        for (int rp = 0; rp < NREP; rp++) {
            // slot 0 carries h(0)=0 with tag 0 (consumed at t=0); others poisoned.
            g_hpair[0][rp][tid] = 0ull;
            for (int m = 1; m < RING; m++)
                g_hpair[m][rp][tid] = 0xFFFFFFFF00000000ull;
        }
    }
    if (tid == 0) {
        float s = 0.f;
        for (int k = 0; k < NHEAD; k++) s += b1[k] * Wout[k];
        g_c0 = s;
    }
}

// ---------------------------------------------------------------------------
// Kernel 1: xg[t, colp] = x[t] . W_ih[grow] + (b_ih+b_hh)[grow], permuted so
// warp u of the LSTM kernel reads one float4 (i,f,g,o for its unit):
//   colp = u*4 + gate,  grow = gate*512 + u.
// ---------------------------------------------------------------------------
__global__ __launch_bounds__(256) void xg_kernel(const float* __restrict__ x,
                                                 const float* __restrict__ W_ih,
                                                 const float* __restrict__ b_ih,
                                                 const float* __restrict__ b_hh) {
    __shared__ float Xs[32][I_DIM];
    int tb    = blockIdx.x;       // 0..1023 (32 timesteps each)
    int cb    = blockIdx.y;       // 0..7    (256 columns each)
    int tid   = threadIdx.x;
    int tbase = tb * 32;

    for (int idx = tid; idx < 32 * I_DIM; idx += 256)
        Xs[idx >> 7][idx & 127] = x[(tbase + (idx >> 7)) * I_DIM + (idx & 127)];
    __syncthreads();

    int col  = cb * 256 + tid;            // permuted column
    int u    = col >> 2;
    int gate = col & 3;
    int grow = gate * 512 + u;
    float bias = b_ih[grow] + b_hh[grow];

    float acc[32];
#pragma unroll
    for (int tt = 0; tt < 32; tt++) acc[tt] = bias;

    const float4* Wr = (const float4*)(W_ih + grow * I_DIM);
    for (int kq = 0; kq < 32; kq++) {
        float4 w4 = Wr[kq];
#pragma unroll
        for (int tt = 0; tt < 32; tt++) {
            float4 x4 = *(const float4*)&Xs[tt][kq * 4];
            acc[tt] += w4.x * x4.x + w4.y * x4.y + w4.z * x4.z + w4.w * x4.w;
        }
    }
#pragma unroll
    for (int tt = 0; tt < 32; tt++)
        g_xg[(tbase + tt) * G_DIM + col] = acc[tt];
}

// ---------------------------------------------------------------------------
// Kernel 2: persistent sequential LSTM. 64 CTAs x 256 threads.
// Warp w of CTA cb owns unit u = cb*8+w (gate rows u, 512+u, 1024+u, 1536+u);
// W_hh slice register-resident. Per step:
//  - each thread polls BOTH its pairs in its CTA's replica (one v2.b64),
//  - ONE barrier (double-buffered hbuf/pbuf),
//  - packed-f32x2 matvec + shfl butterfly (sums land in ALL lanes),
//  - lanes 0-3 redundantly run the deterministic cell; lane l publishes
//    (h, tag=t+1) to replica l (parallel 4-way fan-out, cost of one store).
// Ring safety (proven in R5/R16, unchanged by replication): publishing tag
// t+1 requires passing the step-t poll => all CTAs finished step t-1 => all
// consumed the overwritten tag (t-7) at their step t-7.
// ---------------------------------------------------------------------------
__global__ __launch_bounds__(256, 1) void lstm_kernel(const float* __restrict__ W_hh) {
    __shared__ float hbuf[2][H_DIM];
    __shared__ float pbuf[2][8];
    __shared__ int   dead;
    int tid = threadIdx.x;
    int w   = tid >> 5;
    int l   = tid & 31;
    int cb  = blockIdx.x;
    int u   = cb * 8 + w;
    int rep = cb & (NREP - 1);

    if (tid == 0) dead = 0;

    // Register-resident W_hh: row r (gate) covers h[4l+128m .. +4).
    float4 wr[4][4];
#pragma unroll
    for (int r = 0; r < 4; r++) {
        const float* row = W_hh + (r * 512 + u) * H_DIM;
#pragma unroll
        for (int m = 0; m < 4; m++)
            wr[r][m] = *(const float4*)(row + 4 * l + 128 * m);
    }

    float cstate = 0.f;                        // maintained in lanes 0-3 (identical)
    float vval   = (l == 0) ? g_v[u] : 0.f;

    // Warp-uniform xg float4 (broadcast; one transaction).
    float4 xg4 = *(const float4*)&g_xg[0 * G_DIM + u * 4];
    __syncthreads();

    for (int t = 0; t < T_LEN; t++) {
        int buf = t & 1;

        // Prefetch next step's gate pre-activations (DRAM latency hidden).
        float4 xg_next = make_float4(0.f, 0.f, 0.f, 0.f);
        if (t + 1 < T_LEN)
            xg_next = *(const float4*)&g_xg[(t + 1) * G_DIM + u * 4];

        // Poll both pairs this thread owns in OUR replica (one 16B load; each
        // 8B element individually single-copy atomic).
        {
            const unsigned long long* p0 = &g_hpair[t & (RING - 1)][rep][2 * tid];
            unsigned long long v0, v1;
            unsigned long long want = ((unsigned long long)(unsigned)t) << 32;
            unsigned int spins = 0;
            do {
                asm volatile("ld.relaxed.gpu.global.v2.b64 {%0,%1}, [%2];"
                             : "=l"(v0), "=l"(v1) : "l"(p0) : "memory");
                if (++spins >= WDOG) { dead = 1; break; }     // watchdog
            } while ((v0 & 0xFFFFFFFF00000000ull) != want ||
                     (v1 & 0xFFFFFFFF00000000ull) != want);
            hbuf[buf][2 * tid]     = __uint_as_float((unsigned)v0);
            hbuf[buf][2 * tid + 1] = __uint_as_float((unsigned)v1);
        }
        __syncthreads();          // the ONLY barrier per step
        if (dead) break;

        // Matvec: 4 gate rows x 16 h-elems per lane, packed f32x2.
        unsigned long long acc2[4] = {0ull, 0ull, 0ull, 0ull};
#pragma unroll
        for (int m = 0; m < 4; m++) {
            float4 h4 = *(const float4*)&hbuf[buf][4 * l + 128 * m];   // conflict-free
            unsigned long long hlo = *(const unsigned long long*)&h4.x;
            unsigned long long hhi = *(const unsigned long long*)&h4.z;
#pragma unroll
            for (int r = 0; r < 4; r++) {
                unsigned long long wlo = *(const unsigned long long*)&wr[r][m].x;
                unsigned long long whi = *(const unsigned long long*)&wr[r][m].z;
                acc2[r] = fma2(wlo, hlo, acc2[r]);
                acc2[r] = fma2(whi, hhi, acc2[r]);
            }
        }
        float acc[4];
#pragma unroll
        for (int r = 0; r < 4; r++) {
            unsigned int lo = (unsigned int)acc2[r];
            unsigned int hi = (unsigned int)(acc2[r] >> 32);
            acc[r] = __uint_as_float(lo) + __uint_as_float(hi);
        }
#pragma unroll
        for (int off = 16; off > 0; off >>= 1) {
#pragma unroll
            for (int r = 0; r < 4; r++)
                acc[r] += __shfl_xor_sync(0xffffffffu, acc[r], off);
        }
        // Butterfly leaves the full sums in EVERY lane.

        // Lanes 0-3: redundant deterministic cell; lane l publishes (h, tag)
        // to replica l — 4-way fan-out at the cost of one store.
        if (l < 4) {
            float iv = fsigmoid(acc[0] + xg4.x);
            float fv = fsigmoid(acc[1] + xg4.y);
            float gv = ftanh_fast(acc[2] + xg4.z);
            float ov = fsigmoid(acc[3] + xg4.w);
            cstate = fv * cstate + iv * gv;
            float hv = ov * ftanh_fast(cstate);
            unsigned long long pairv =
                ((unsigned long long)(unsigned)(t + 1) << 32) |
                (unsigned long long)__float_as_uint(hv);
            asm volatile("st.relaxed.gpu.global.b64 [%0], %1;"
                         :: "l"(&g_hpair[(t + 1) & (RING - 1)][l][u]), "l"(pairv)
                         : "memory");
            if (l == 0) pbuf[buf][w] = hv * vval;
        }

        // Off critical path: previous step's head partial (pbuf[buf^1] was
        // completed by all warps before they arrived at this step's barrier).
        if (tid == 0 && t > 0) {
            float* pb = pbuf[buf ^ 1];
            float s = pb[0] + pb[1] + pb[2] + pb[3]
                    + pb[4] + pb[5] + pb[6] + pb[7];
            g_part[(t - 1) * NCTA + cb] = s;
        }
        xg4 = xg_next;
    }

    __syncthreads();
    if (tid == 0) {   // final step's head partial
        float* pb = pbuf[(T_LEN - 1) & 1];
        float s = pb[0] + pb[1] + pb[2] + pb[3] + pb[4] + pb[5] + pb[6] + pb[7];
        g_part[(T_LEN - 1) * NCTA + cb] = s;
    }
}

// ---------------------------------------------------------------------------
// Kernel 3: out[t] = c0 + sum_cb g_part[t][cb]
// ---------------------------------------------------------------------------
__global__ void head_kernel(float* __restrict__ out) {
    int t = blockIdx.x * blockDim.x + threadIdx.x;
    if (t >= T_LEN) return;
    float s = g_c0;
    const float4* p = (const float4*)&g_part[t * NCTA];
#pragma unroll
    for (int q = 0; q < NCTA / 4; q++) {
        float4 v = p[q];
        s += v.x + v.y + v.z + v.w;
    }
    out[t] = s;
}

// ---------------------------------------------------------------------------
extern "C" void kernel_launch(void* const* d_in, const int* in_sizes, int n_in,
                              void* d_out, int out_size) {
    const float* x    = (const float*)d_in[0];
    const float* W_ih = (const float*)d_in[1];
    const float* W_hh = (const float*)d_in[2];
    const float* b_ih = (const float*)d_in[3];
    const float* b_hh = (const float*)d_in[4];
    const float* W1   = (const float*)d_in[5];
    const float* b1   = (const float*)d_in[6];
    const float* Wout = (const float*)d_in[7];
    float* out = (float*)d_out;

    (void)in_sizes; (void)n_in; (void)out_size;

    prep_kernel<<<1, 512>>>(W1, b1, Wout);
    dim3 gx(T_LEN / 32, G_DIM / 256);
    xg_kernel<<<gx, 256>>>(x, W_ih, b_ih, b_hh);
    lstm_kernel<<<NCTA, 256>>>(W_hh);
    head_kernel<<<T_LEN / 256, 256>>>(out);
}